// round 7
// baseline (speedup 1.0000x reference)
#include <cuda_runtime.h>

#define E_DIM 1024
#define SEQ   2048
#define NH    16
#define HD    64
#define MTOK  4096
#define ATT_SCALE 0.125f
#define XN ((size_t)MTOK * E_DIM)
#define WN ((size_t)E_DIM * E_DIM)

// All of these hold PERMUTED column layouts: within each 8-col group,
// order is [0,4,1,5,2,6,3,7] so mma fragment pairs (j, j+4) are adjacent.
__device__ float g_q[XN];
__device__ float g_k[XN];
__device__ float g_vT[XN];     // [B*H][HD][SEQ], tokens permuted per-8
__device__ float g_ctx[XN];
__device__ float g_x[XN];
__device__ float g_wq[WN];
__device__ float g_wk[WN];
__device__ float g_wv[WN];
__device__ float g_wo[WN];

__device__ __forceinline__ unsigned f2tf(float x) {
    unsigned r;
    asm("cvt.rna.tf32.f32 %0, %1;" : "=r"(r) : "f"(x));
    return r;
}
__device__ __forceinline__ float f2tff(float x) {
    return __uint_as_float(f2tf(x));
}

__device__ __forceinline__ void mma_tf32(float* c, const unsigned* a,
                                         unsigned b0, unsigned b1) {
    asm volatile(
        "mma.sync.aligned.m16n8k8.row.col.f32.tf32.tf32.f32 "
        "{%0,%1,%2,%3}, {%4,%5,%6,%7}, {%8,%9}, {%0,%1,%2,%3};\n"
        : "+f"(c[0]), "+f"(c[1]), "+f"(c[2]), "+f"(c[3])
        : "r"(a[0]), "r"(a[1]), "r"(a[2]), "r"(a[3]), "r"(b0), "r"(b1));
}

__device__ __forceinline__ unsigned sptr(const void* p) {
    return (unsigned)__cvta_generic_to_shared(p);
}
__device__ __forceinline__ void cp16(unsigned d, const float* s) {
    asm volatile("cp.async.cg.shared.global [%0], [%1], 16;\n" :: "r"(d), "l"(s));
}
__device__ __forceinline__ void cp_commit() {
    asm volatile("cp.async.commit_group;\n");
}
template <int N>
__device__ __forceinline__ void cp_wait() {
    asm volatile("cp.async.wait_group %0;\n" :: "n"(N));
}

// ---------------------------------------------------------------------------
// Prep: tf32-round AND column-permute x + 4 weights. Thread = one 8-col group.
// out[0..7] = in[0],in[4],in[1],in[5],in[2],in[6],in[3],in[7]
// ---------------------------------------------------------------------------
__global__ void __launch_bounds__(256)
k_prep(const float* __restrict__ x,
       const float* __restrict__ wq, const float* __restrict__ wk,
       const float* __restrict__ wv, const float* __restrict__ wo)
{
    size_t i = ((size_t)blockIdx.x * 256 + threadIdx.x) * 8;
    const float* s; float* d; size_t off;
    if (i < XN)               { s = x;  d = g_x;  off = i; }
    else if (i < XN + WN)     { s = wq; d = g_wq; off = i - XN; }
    else if (i < XN + 2 * WN) { s = wk; d = g_wk; off = i - XN - WN; }
    else if (i < XN + 3 * WN) { s = wv; d = g_wv; off = i - XN - 2 * WN; }
    else                      { s = wo; d = g_wo; off = i - XN - 3 * WN; }
    float4 lo = *(const float4*)(s + off);
    float4 hi = *(const float4*)(s + off + 4);
    *(float4*)(d + off) =
        make_float4(f2tff(lo.x), f2tff(hi.x), f2tff(lo.y), f2tff(hi.y));
    *(float4*)(d + off + 4) =
        make_float4(f2tff(lo.z), f2tff(hi.z), f2tff(lo.w), f2tff(hi.w));
}

// ---------------------------------------------------------------------------
// tf32 GEMM: C = A[M,K]*W[N,K]^T + bias. Tile 128x128x16, 4-stage cp.async.
// 8 warps (4x2), warp = 32x64. Frag loads are LDS.64 (permuted layout).
// MODE: 0 plain out, 1 q/k (permuted+rounded), 2 V^T (token-permuted+rounded).
// ---------------------------------------------------------------------------
#define KC  16
#define AST 24                  // words/row: banks 24g+2tig distinct
#define GST (128 * AST)

template <int MODE>
__device__ __forceinline__ void gemm_body(const float* __restrict__ A,
                                          const float* __restrict__ W,
                                          const float* __restrict__ bias,
                                          float* __restrict__ C,
                                          unsigned* sm)
{
    const int tid  = threadIdx.x;
    const int lane = tid & 31, warp = tid >> 5;
    const int g = lane >> 2, tig = lane & 3;
    const int m0 = (warp >> 1) * 32;
    const int n0 = (warp & 1) * 64;
    const int row0 = blockIdx.y * 128;
    const int col0 = blockIdx.x * 128;
    const int pp0 = (tig < 2) ? 4 * tig : 4 * tig - 7;  // perm pos of col 2*tig

    const int lrow = tid >> 1;
    const int lcb  = (tid & 1) * 8;
    const float* Ag = A + (size_t)(row0 + lrow) * E_DIM + lcb;
    const float* Wg = W + (size_t)(col0 + lrow) * E_DIM + lcb;
    const unsigned dA0 = sptr(sm + lrow * AST + lcb);
    const unsigned dW0 = dA0 + GST * 4;
    const unsigned stageB = 2 * GST * 4;

    float acc[2][8][4];
#pragma unroll
    for (int mi = 0; mi < 2; mi++)
#pragma unroll
        for (int ni = 0; ni < 8; ni++)
#pragma unroll
            for (int j = 0; j < 4; j++) acc[mi][ni][j] = 0.f;

#pragma unroll
    for (int s = 0; s < 3; s++) {
        const int ko = s * KC;
        cp16(dA0 + s * stageB,      Ag + ko);
        cp16(dA0 + s * stageB + 16, Ag + ko + 4);
        cp16(dW0 + s * stageB,      Wg + ko);
        cp16(dW0 + s * stageB + 16, Wg + ko + 4);
        cp_commit();
    }

    const int NKT = E_DIM / KC;
    for (int kt = 0; kt < NKT; kt++) {
        cp_wait<2>();
        __syncthreads();
        if (kt + 3 < NKT) {
            const unsigned sb = ((kt + 3) & 3) * stageB;
            const int ko = (kt + 3) * KC;
            cp16(dA0 + sb,      Ag + ko);
            cp16(dA0 + sb + 16, Ag + ko + 4);
            cp16(dW0 + sb,      Wg + ko);
            cp16(dW0 + sb + 16, Wg + ko + 4);
        }
        cp_commit();

        const unsigned* As = sm + (kt & 3) * 2 * GST;
        const unsigned* Ws = As + GST;
#pragma unroll
        for (int kk = 0; kk < KC; kk += 8) {
            unsigned a[2][4];
            uint2 bb[8];
#pragma unroll
            for (int mi = 0; mi < 2; mi++) {
                const int row = m0 + mi * 16;
                uint2 a0 = *(const uint2*)&As[(row + g) * AST + kk + 2 * tig];
                uint2 a1 = *(const uint2*)&As[(row + g + 8) * AST + kk + 2 * tig];
                a[mi][0] = a0.x; a[mi][1] = a1.x; a[mi][2] = a0.y; a[mi][3] = a1.y;
            }
#pragma unroll
            for (int ni = 0; ni < 8; ni++)
                bb[ni] = *(const uint2*)&Ws[(n0 + ni * 8 + g) * AST + kk + 2 * tig];
#pragma unroll
            for (int mi = 0; mi < 2; mi++)
#pragma unroll
                for (int ni = 0; ni < 8; ni++)
                    mma_tf32(acc[mi][ni], a[mi], bb[ni].x, bb[ni].y);
        }
    }

#pragma unroll
    for (int mi = 0; mi < 2; mi++) {
#pragma unroll
        for (int ni = 0; ni < 8; ni++) {
            const int row = row0 + m0 + mi * 16;
            const int cbase = col0 + n0 + ni * 8;
            const float bx = bias[cbase + 2 * tig];
            const float by = bias[cbase + 2 * tig + 1];
            if (MODE == 2) {
                // g_vT[(b*NH+h)*HD + dim][token'], tokens permuted per-8 by g
                const int gp = (g < 4) ? 2 * g : 2 * g - 7;
#pragma unroll
                for (int rr = 0; rr < 2; rr++) {
                    const int r = row + g + rr * 8;
                    const int b = r >> 11;
                    const int sp = (r & 2047) - g + gp;
                    const int col = cbase + 2 * tig;
                    const size_t d0 =
                        ((size_t)(b * NH + (col >> 6)) * HD + (col & 63)) * SEQ + sp;
                    C[d0]       = f2tff(acc[mi][ni][2 * rr + 0] + bx);
                    C[d0 + SEQ] = f2tff(acc[mi][ni][2 * rr + 1] + by);
                }
            } else if (MODE == 1) {
                // permuted + rounded scalar stores
                C[(size_t)(row + g) * E_DIM + cbase + pp0]     = f2tff(acc[mi][ni][0] + bx);
                C[(size_t)(row + g) * E_DIM + cbase + pp0 + 2] = f2tff(acc[mi][ni][1] + by);
                C[(size_t)(row + g + 8) * E_DIM + cbase + pp0]     = f2tff(acc[mi][ni][2] + bx);
                C[(size_t)(row + g + 8) * E_DIM + cbase + pp0 + 2] = f2tff(acc[mi][ni][3] + by);
            } else {
                const int col = cbase + 2 * tig;
                *(float2*)&C[(size_t)(row + g) * E_DIM + col] =
                    make_float2(acc[mi][ni][0] + bx, acc[mi][ni][1] + by);
                *(float2*)&C[(size_t)(row + g + 8) * E_DIM + col] =
                    make_float2(acc[mi][ni][2] + bx, acc[mi][ni][3] + by);
            }
        }
    }
}

__global__ void __launch_bounds__(256, 2)
k_gemm_qkv(const float* __restrict__ bq, const float* __restrict__ bk,
           const float* __restrict__ bv)
{
    extern __shared__ unsigned dynsm[];
    if (blockIdx.z == 0)      gemm_body<1>(g_x, g_wq, bq, g_q,  dynsm);
    else if (blockIdx.z == 1) gemm_body<1>(g_x, g_wk, bk, g_k,  dynsm);
    else                      gemm_body<2>(g_x, g_wv, bv, g_vT, dynsm);
}

__global__ void __launch_bounds__(256, 2)
k_gemm_out(const float* __restrict__ bo, float* __restrict__ Cout)
{
    extern __shared__ unsigned dynsm[];
    gemm_body<0>(g_ctx, g_wo, bo, Cout, dynsm);
}

// ---------------------------------------------------------------------------
// Flash attention tf32. CTA = (b,h,128-q tile), 256 thr = 8 warps.
// K + V^T 2-stage cp.async. All frag loads LDS.64 via permuted layouts.
// ---------------------------------------------------------------------------
#define FS   72                 // words/row: banks 8g+2tig distinct
#define FSTG (2 * 64 * FS)

__global__ void __launch_bounds__(256, 2) k_flash()
{
    extern __shared__ unsigned sm[];
    unsigned* Ps = sm + 2 * FSTG;   // 128 x FS (Q staging, then P)

    const int tid  = threadIdx.x;
    const int lane = tid & 31, warp = tid >> 5;
    const int g = lane >> 2, tig = lane & 3;
    const int pp0 = (tig < 2) ? 4 * tig : 4 * tig - 7;
    const int qt = blockIdx.x, h = blockIdx.y, b = blockIdx.z;
    const size_t base   = (size_t)b * SEQ * E_DIM + (size_t)h * HD;
    const size_t vtbase = (size_t)(b * NH + h) * HD * SEQ;
    const int wr = warp * 16;

    const int lr = tid >> 2;            // 0..63
    const int c  = (tid & 3) * 16;
    const float* Kg = g_k  + base   + (size_t)lr * E_DIM + c;
    const float* Vg = g_vT + vtbase + (size_t)lr * SEQ   + c;
    const unsigned dK0 = sptr(sm + lr * FS + c);
    const unsigned dV0 = dK0 + 64 * FS * 4;

#pragma unroll
    for (int j = 0; j < 4; j++) {
        cp16(dK0 + 16 * j, Kg + 4 * j);
        cp16(dV0 + 16 * j, Vg + 4 * j);
    }
    cp_commit();

    // stage Q (128x64, permuted+rounded) into Ps
    for (int i = tid; i < 128 * 16; i += 256) {
        const int rr = i >> 4, c4 = (i & 15) << 2;
        *(float4*)&Ps[rr * FS + c4] =
            *(const float4*)&g_q[base + (size_t)(qt * 128 + rr) * E_DIM + c4];
    }
    __syncthreads();

    unsigned qa[8][4];
#pragma unroll
    for (int ks = 0; ks < 8; ks++) {
        uint2 q0 = *(const uint2*)&Ps[(wr + g) * FS + 8 * ks + 2 * tig];
        uint2 q1 = *(const uint2*)&Ps[(wr + g + 8) * FS + 8 * ks + 2 * tig];
        qa[ks][0] = q0.x; qa[ks][1] = q1.x; qa[ks][2] = q0.y; qa[ks][3] = q1.y;
    }

    float o[8][4];
#pragma unroll
    for (int ni = 0; ni < 8; ni++)
#pragma unroll
        for (int j = 0; j < 4; j++) o[ni][j] = 0.f;
    float m0 = -3.0e38f, m1 = -3.0e38f, l0 = 0.f, l1 = 0.f;

    const int NT = SEQ / 64;
    for (int kt = 0; kt < NT; kt++) {
        __syncthreads();
        if (kt + 1 < NT) {
            const unsigned dd = ((kt + 1) & 1) * FSTG * 4;
            const float* kp = Kg + (size_t)(kt + 1) * 64 * E_DIM;
            const float* vp = Vg + (kt + 1) * 64;
#pragma unroll
            for (int j = 0; j < 4; j++) {
                cp16(dK0 + dd + 16 * j, kp + 4 * j);
                cp16(dV0 + dd + 16 * j, vp + 4 * j);
            }
        }
        cp_commit();
        cp_wait<1>();
        __syncthreads();

        const unsigned* Ks = sm + (kt & 1) * FSTG;
        const unsigned* Vs = Ks + 64 * FS;

        // S = Q K^T
        float s[8][4];
#pragma unroll
        for (int ni = 0; ni < 8; ni++)
#pragma unroll
            for (int j = 0; j < 4; j++) s[ni][j] = 0.f;
#pragma unroll
        for (int ks = 0; ks < 8; ks++) {
#pragma unroll
            for (int ni = 0; ni < 8; ni++) {
                uint2 kb = *(const uint2*)&Ks[(8 * ni + g) * FS + 8 * ks + 2 * tig];
                mma_tf32(s[ni], qa[ks], kb.x, kb.y);
            }
        }

        // online softmax
        float mx0 = -3.0e38f, mx1 = -3.0e38f;
#pragma unroll
        for (int ni = 0; ni < 8; ni++) {
            s[ni][0] *= ATT_SCALE; s[ni][1] *= ATT_SCALE;
            s[ni][2] *= ATT_SCALE; s[ni][3] *= ATT_SCALE;
            mx0 = fmaxf(mx0, fmaxf(s[ni][0], s[ni][1]));
            mx1 = fmaxf(mx1, fmaxf(s[ni][2], s[ni][3]));
        }
        mx0 = fmaxf(mx0, __shfl_xor_sync(0xffffffffu, mx0, 1));
        mx0 = fmaxf(mx0, __shfl_xor_sync(0xffffffffu, mx0, 2));
        mx1 = fmaxf(mx1, __shfl_xor_sync(0xffffffffu, mx1, 1));
        mx1 = fmaxf(mx1, __shfl_xor_sync(0xffffffffu, mx1, 2));
        const float mn0 = fmaxf(m0, mx0), mn1 = fmaxf(m1, mx1);
        const float al0 = __expf(m0 - mn0), al1 = __expf(m1 - mn1);
        float s0 = 0.f, s1 = 0.f;
#pragma unroll
        for (int ni = 0; ni < 8; ni++) {
            float p0 = __expf(s[ni][0] - mn0);
            float p1 = __expf(s[ni][1] - mn0);
            float p2 = __expf(s[ni][2] - mn1);
            float p3 = __expf(s[ni][3] - mn1);
            s0 += p0 + p1; s1 += p2 + p3;
            // P -> smem at permuted positions (pp0, pp0+2)
            Ps[(wr + g) * FS + 8 * ni + pp0]         = f2tf(p0);
            Ps[(wr + g) * FS + 8 * ni + pp0 + 2]     = f2tf(p1);
            Ps[(wr + g + 8) * FS + 8 * ni + pp0]     = f2tf(p2);
            Ps[(wr + g + 8) * FS + 8 * ni + pp0 + 2] = f2tf(p3);
        }
        s0 += __shfl_xor_sync(0xffffffffu, s0, 1);
        s0 += __shfl_xor_sync(0xffffffffu, s0, 2);
        s1 += __shfl_xor_sync(0xffffffffu, s1, 1);
        s1 += __shfl_xor_sync(0xffffffffu, s1, 2);
        l0 = l0 * al0 + s0;
        l1 = l1 * al1 + s1;
        m0 = mn0; m1 = mn1;
#pragma unroll
        for (int ni = 0; ni < 8; ni++) {
            o[ni][0] *= al0; o[ni][1] *= al0;
            o[ni][2] *= al1; o[ni][3] *= al1;
        }
        __syncwarp();

        // O += P V
#pragma unroll
        for (int ks = 0; ks < 8; ks++) {
            unsigned pa[4];
            uint2 p0 = *(const uint2*)&Ps[(wr + g) * FS + 8 * ks + 2 * tig];
            uint2 p1 = *(const uint2*)&Ps[(wr + g + 8) * FS + 8 * ks + 2 * tig];
            pa[0] = p0.x; pa[1] = p1.x; pa[2] = p0.y; pa[3] = p1.y;
#pragma unroll
            for (int ni = 0; ni < 8; ni++) {
                uint2 vb = *(const uint2*)&Vs[(8 * ni + g) * FS + 8 * ks + 2 * tig];
                mma_tf32(o[ni], pa, vb.x, vb.y);
            }
        }
    }

    // epilogue: permuted + rounded scalar stores into g_ctx
    const float i0 = 1.0f / l0, i1 = 1.0f / l1;
    const int grow = qt * 128 + wr;
#pragma unroll
    for (int ni = 0; ni < 8; ni++) {
        const int cb = 8 * ni;
        float* r0 = &g_ctx[base + (size_t)(grow + g) * E_DIM + cb];
        float* r1 = &g_ctx[base + (size_t)(grow + g + 8) * E_DIM + cb];
        r0[pp0]     = f2tff(o[ni][0] * i0);
        r0[pp0 + 2] = f2tff(o[ni][1] * i0);
        r1[pp0]     = f2tff(o[ni][2] * i1);
        r1[pp0 + 2] = f2tff(o[ni][3] * i1);
    }
}

// ---------------------------------------------------------------------------

extern "C" void kernel_launch(void* const* d_in, const int* in_sizes, int n_in,
                              void* d_out, int out_size)
{
    const float* x  = (const float*)d_in[0];
    const float* qw = (const float*)d_in[1];
    const float* qb = (const float*)d_in[2];
    const float* kw = (const float*)d_in[3];
    const float* kb = (const float*)d_in[4];
    const float* vw = (const float*)d_in[5];
    const float* vb = (const float*)d_in[6];
    const float* ow = (const float*)d_in[7];
    const float* ob = (const float*)d_in[8];
    float* out = (float*)d_out;

    const int gemm_smem  = 4 * 2 * GST * (int)sizeof(unsigned);            // 98304
    const int flash_smem = (2 * FSTG + 128 * FS) * (int)sizeof(unsigned);  // 110592
    cudaFuncSetAttribute(k_gemm_qkv, cudaFuncAttributeMaxDynamicSharedMemorySize, gemm_smem);
    cudaFuncSetAttribute(k_gemm_out, cudaFuncAttributeMaxDynamicSharedMemorySize, gemm_smem);
    cudaFuncSetAttribute(k_flash,    cudaFuncAttributeMaxDynamicSharedMemorySize, flash_smem);

    k_prep<<<(unsigned)((XN + 4 * WN) / 8 / 256), 256>>>(x, qw, kw, vw, ow);

    dim3 gq(E_DIM / 128, MTOK / 128, 3);
    k_gemm_qkv<<<gq, 256, gemm_smem>>>(qb, kb, vb);

    dim3 gf(SEQ / 128, NH, 2);
    k_flash<<<gf, 256, flash_smem>>>();

    dim3 go(E_DIM / 128, MTOK / 128, 1);
    k_gemm_out<<<go, 256, gemm_smem>>>(ob, out);
}